// round 7
// baseline (speedup 1.0000x reference)
#include <cuda_runtime.h>
#include <math.h>

#define NN 30000
#define NE 480000
#define DDIM 128
#define EDIM 64
#define NH 8

// ---- scratch (__device__ globals; allocation is forbidden) ----
__device__ float g_Q[NN*DDIM], g_K[NN*DDIM], g_V[NN*DDIM];
__device__ float g_big[NE*DDIM];                 // Pe, later e-FFN mid
__device__ float g_score[NE*NH], g_sc[NE*NH], g_z[NN*NH];
__device__ float g_hattn[NN*DDIM];
__device__ float g_hb[NN*DDIM];
__device__ float g_hmid[NN*2*DDIM];
__device__ float g_eres[NE*EDIM], g_ebn[NE*EDIM];
__device__ float g_Wc[NH*EDIM], g_bc[EDIM];
__device__ float g_S[4][DDIM], g_Qs[4][DDIM], g_mean[4][DDIM], g_rstd[4][DDIM];
// stat slots: 0=BN1e 1=BN2e 2=BN1h 3=BN2h

__global__ void k_init() {
    int t = blockIdx.x*blockDim.x + threadIdx.x, st = gridDim.x*blockDim.x;
    for (int i = t; i < NN*DDIM; i += st) g_hattn[i] = 0.f;
    for (int i = t; i < NN*NH;  i += st) g_z[i] = 0.f;
    if (t < 4*DDIM) { (&g_S[0][0])[t] = 0.f; (&g_Qs[0][0])[t] = 0.f; }
}

// fold Wc = W_ep @ W_Oe, bc = b_ep @ W_Oe + b_Oe
__global__ void k_fold(const float* __restrict__ Wep, const float* __restrict__ bep,
                       const float* __restrict__ WOe, const float* __restrict__ bOe) {
    int t = threadIdx.x;                 // 512 threads
    int h = t >> 6, j = t & 63;
    float a = 0.f;
    for (int k = 0; k < EDIM; k++) a += Wep[h*EDIM + k] * WOe[k*EDIM + j];
    g_Wc[t] = a;
    if (t < EDIM) {
        float b = bOe[t];
        for (int k = 0; k < EDIM; k++) b += bep[k] * WOe[k*EDIM + t];
        g_bc[t] = b;
    }
}

// generic weight-stationary GEMM: out[M,DOUT] = in[M,DIN] @ W + bias, opt ReLU
template<int DIN, int DOUT, bool RELU>
__global__ void k_gemm(const float* __restrict__ in, const float* __restrict__ W,
                       const float* __restrict__ bias, float* __restrict__ out, int M) {
    extern __shared__ float sm[];
    float* Ws = sm;
    float* rows = sm + DIN*DOUT;
    const int tid = threadIdx.x, l = tid & 31, wid = tid >> 5, nw = blockDim.x >> 5;
    for (int i = tid; i < DIN*DOUT/4; i += blockDim.x)
        ((float4*)Ws)[i] = ((const float4*)W)[i];
    __syncthreads();
    float* mr = rows + wid*4*DIN;
    const int nt = M/4;
    for (int t = blockIdx.x*nw + wid; t < nt; t += gridDim.x*nw) {
        const int r0 = t*4;
        for (int i = l; i < DIN; i += 32)                 // 4 rows = DIN float4s
            ((float4*)mr)[i] = ((const float4*)(in + (size_t)r0*DIN))[i];
        __syncwarp();
        if constexpr (DOUT >= 128) {
            constexpr int G = DOUT/128;
            float4 acc[4][G];
#pragma unroll
            for (int j = 0; j < 4; j++)
#pragma unroll
                for (int g = 0; g < G; g++)
                    acc[j][g] = bias ? ((const float4*)bias)[l + 32*g]
                                     : make_float4(0.f,0.f,0.f,0.f);
#pragma unroll 4
            for (int k = 0; k < DIN; k++) {
                float4 w[G];
#pragma unroll
                for (int g = 0; g < G; g++) w[g] = ((float4*)(Ws + k*DOUT))[l + 32*g];
#pragma unroll
                for (int j = 0; j < 4; j++) {
                    float a = mr[j*DIN + k];
#pragma unroll
                    for (int g = 0; g < G; g++) {
                        acc[j][g].x += a*w[g].x; acc[j][g].y += a*w[g].y;
                        acc[j][g].z += a*w[g].z; acc[j][g].w += a*w[g].w;
                    }
                }
            }
#pragma unroll
            for (int j = 0; j < 4; j++)
#pragma unroll
                for (int g = 0; g < G; g++) {
                    float4 v = acc[j][g];
                    if (RELU) { v.x=fmaxf(v.x,0.f); v.y=fmaxf(v.y,0.f);
                                v.z=fmaxf(v.z,0.f); v.w=fmaxf(v.w,0.f); }
                    ((float4*)(out + (size_t)(r0+j)*DOUT))[l + 32*g] = v;
                }
        } else {  // DOUT == 64
            float2 acc[4];
#pragma unroll
            for (int j = 0; j < 4; j++)
                acc[j] = bias ? ((const float2*)bias)[l] : make_float2(0.f,0.f);
#pragma unroll 4
            for (int k = 0; k < DIN; k++) {
                float2 w = ((float2*)(Ws + k*DOUT))[l];
#pragma unroll
                for (int j = 0; j < 4; j++) {
                    float a = mr[j*DIN + k];
                    acc[j].x += a*w.x; acc[j].y += a*w.y;
                }
            }
#pragma unroll
            for (int j = 0; j < 4; j++) {
                float2 v = acc[j];
                if (RELU) { v.x = fmaxf(v.x,0.f); v.y = fmaxf(v.y,0.f); }
                ((float2*)(out + (size_t)(r0+j)*DOUT))[l] = v;
            }
        }
        __syncwarp();
    }
}

template<int DIN, int DOUT, bool RELU>
static void gemm(const float* in, const float* W, const float* b, float* out, int M) {
    const int thr = 512, nw = 16;
    size_t sh = (size_t)(DIN*DOUT + nw*4*DIN) * sizeof(float);
    cudaFuncSetAttribute(k_gemm<DIN,DOUT,RELU>,
                         cudaFuncAttributeMaxDynamicSharedMemorySize, (int)sh);
    k_gemm<DIN,DOUT,RELU><<<296, thr, sh>>>(in, W, b, out, M);
}

// per-edge score: s = sum(Q[dst]*K[src]*Pe)/4; exp(clip); z scatter
__global__ void k_score(const int* __restrict__ ei) {
    const int tid = threadIdx.x, l = tid & 31;
    int gw = (blockIdx.x*blockDim.x + tid) >> 5, tot = (gridDim.x*blockDim.x) >> 5;
    for (int e = gw; e < NE; e += tot) {
        int s = ei[e], d = ei[NE + e];
        float4 q = ((const float4*)g_Q)[d*32 + l];
        float4 k = ((const float4*)g_K)[s*32 + l];
        float4 p = ((const float4*)g_big)[e*32 + l];
        float sc = q.x*k.x*p.x + q.y*k.y*p.y + q.z*k.z*p.z + q.w*k.w*p.w;
        sc += __shfl_xor_sync(0xffffffffu, sc, 1);
        sc += __shfl_xor_sync(0xffffffffu, sc, 2);
        if ((l & 3) == 0) {
            int h = l >> 2;
            float r = sc * 0.25f;                       // 1/sqrt(16)
            g_score[(size_t)e*NH + h] = r;
            float ex = expf(fminf(fmaxf(r, -5.f), 5.f));
            g_sc[(size_t)e*NH + h] = ex;
            atomicAdd(&g_z[(size_t)d*NH + h], ex);
        }
    }
}

// per-edge: alpha = sc/(z+eps); hattn[dst] += V[src]*alpha  (vector RED)
__global__ void k_alpha(const int* __restrict__ ei) {
    const int tid = threadIdx.x, l = tid & 31;
    int gw = (blockIdx.x*blockDim.x + tid) >> 5, tot = (gridDim.x*blockDim.x) >> 5;
    for (int e = gw; e < NE; e += tot) {
        int s = ei[e], d = ei[NE + e];
        int h = l >> 2;
        float a = g_sc[(size_t)e*NH + h] / (g_z[(size_t)d*NH + h] + 1e-6f);
        float4 v = ((const float4*)g_V)[s*32 + l];
        atomicAdd(((float4*)(g_hattn + (size_t)d*DDIM)) + l,
                  make_float4(v.x*a, v.y*a, v.z*a, v.w*a));
    }
}

// e_res = edge_attr + score@Wc + bc; BN1e stats
__global__ void k_elin(const float* __restrict__ ea) {
    const int tid = threadIdx.x, l = tid & 31;
    int gw = (blockIdx.x*blockDim.x + tid) >> 5, tot = (gridDim.x*blockDim.x) >> 5;
    float2 w[NH];
#pragma unroll
    for (int h = 0; h < NH; h++) w[h] = ((const float2*)(g_Wc + h*EDIM))[l];
    float2 bc = ((const float2*)g_bc)[l];
    float s0=0.f, s1=0.f, q0=0.f, q1=0.f;
    for (int e = gw; e < NE; e += tot) {
        float2 acc = bc;
#pragma unroll
        for (int h = 0; h < NH; h++) {
            float sv = g_score[(size_t)e*NH + h];
            acc.x += sv*w[h].x; acc.y += sv*w[h].y;
        }
        float2 eav = ((const float2*)ea)[e*32 + l];
        float2 r = make_float2(eav.x + acc.x, eav.y + acc.y);
        ((float2*)g_eres)[e*32 + l] = r;
        s0 += r.x; q0 += r.x*r.x; s1 += r.y; q1 += r.y*r.y;
    }
    atomicAdd(&g_S[0][2*l], s0);   atomicAdd(&g_S[0][2*l+1], s1);
    atomicAdd(&g_Qs[0][2*l], q0);  atomicAdd(&g_Qs[0][2*l+1], q1);
}

// out = a + b, accumulate per-channel stats into slot
template<int C>
__global__ void k_addstats(const float* __restrict__ a, const float* __restrict__ b,
                           float* __restrict__ out, int slot, int M) {
    constexpr int SH = (C == 128) ? 7 : 6;
    int t = blockIdx.x*blockDim.x + threadIdx.x;
    int c = t & (C - 1);
    int r = t >> SH, rs = (gridDim.x*blockDim.x) >> SH;
    float s = 0.f, q = 0.f;
    for (; r < M; r += rs) {
        size_t i = (size_t)r*C + c;
        float v = a[i] + b[i];
        out[i] = v; s += v; q += v*v;
    }
    atomicAdd(&g_S[slot][c], s); atomicAdd(&g_Qs[slot][c], q);
}

__global__ void k_bnfin(int slot, int C, float invn) {
    int i = threadIdx.x;
    if (i < C) {
        float mu = g_S[slot][i] * invn;
        float var = g_Qs[slot][i] * invn - mu*mu;
        g_mean[slot][i] = mu;
        g_rstd[slot][i] = rsqrtf(var + 1e-5f);
    }
}

template<int C>
__global__ void k_bnapply(const float* __restrict__ in, float* __restrict__ out,
                          const float* __restrict__ ga, const float* __restrict__ be,
                          int slot, size_t total) {
    size_t i0 = (size_t)blockIdx.x*blockDim.x + threadIdx.x;
    size_t st = (size_t)gridDim.x*blockDim.x;       // multiple of C by launch config
    int c = (int)(i0 & (C - 1));
    float sc = ga[c] * g_rstd[slot][c];
    float sh = be[c] - g_mean[slot][c] * sc;
    for (size_t i = i0; i < total; i += st) out[i] = in[i]*sc + sh;
}

extern "C" void kernel_launch(void* const* d_in, const int* in_sizes, int n_in,
                              void* d_out, int out_size) {
    const float* x   = (const float*)d_in[0];
    const int*   ei  = (const int*)  d_in[1];
    const float* ea  = (const float*)d_in[2];
    const float *Wq = (const float*)d_in[3], *Wk = (const float*)d_in[4];
    const float *Wv = (const float*)d_in[5], *We = (const float*)d_in[6];
    const float *WOh = (const float*)d_in[7],  *bOh = (const float*)d_in[8];
    const float *Wep = (const float*)d_in[9],  *bep = (const float*)d_in[10];
    const float *WOe = (const float*)d_in[11], *bOe = (const float*)d_in[12];
    const float *Wh1 = (const float*)d_in[13], *bh1 = (const float*)d_in[14];
    const float *Wh2 = (const float*)d_in[15], *bh2 = (const float*)d_in[16];
    const float *We1 = (const float*)d_in[17], *be1 = (const float*)d_in[18];
    const float *We2 = (const float*)d_in[19], *be2 = (const float*)d_in[20];
    const float *g1h = (const float*)d_in[21], *B1h = (const float*)d_in[22];
    const float *g1e = (const float*)d_in[23], *B1e = (const float*)d_in[24];
    const float *g2h = (const float*)d_in[25], *B2h = (const float*)d_in[26];
    const float *g2e = (const float*)d_in[27], *B2e = (const float*)d_in[28];
    float* out_h = (float*)d_out;
    float* out_e = out_h + (size_t)NN*DDIM;

    float *pQ, *pK, *pV, *pBig, *pHat, *pHb, *pHmid, *pEres, *pEbn;
    cudaGetSymbolAddress((void**)&pQ, g_Q);
    cudaGetSymbolAddress((void**)&pK, g_K);
    cudaGetSymbolAddress((void**)&pV, g_V);
    cudaGetSymbolAddress((void**)&pBig, g_big);
    cudaGetSymbolAddress((void**)&pHat, g_hattn);
    cudaGetSymbolAddress((void**)&pHb, g_hb);
    cudaGetSymbolAddress((void**)&pHmid, g_hmid);
    cudaGetSymbolAddress((void**)&pEres, g_eres);
    cudaGetSymbolAddress((void**)&pEbn, g_ebn);

    k_init<<<592, 256>>>();
    k_fold<<<1, 512>>>(Wep, bep, WOe, bOe);

    // attention projections
    gemm<128,128,false>(x, Wq, nullptr, pQ, NN);
    gemm<128,128,false>(x, Wk, nullptr, pK, NN);
    gemm<128,128,false>(x, Wv, nullptr, pV, NN);
    gemm<64,128,false>(ea, We, nullptr, pBig, NE);        // Pe

    k_score<<<592, 256>>>(ei);
    k_alpha<<<592, 256>>>(ei);
    k_elin<<<592, 256>>>(ea);                             // e_res + BN1e stats
    k_bnfin<<<1, 128>>>(0, EDIM, 1.f/NE);

    // h path
    gemm<128,128,false>(pHat, WOh, bOh, pQ, NN);          // tmp -> pQ (Q dead)
    k_addstats<128><<<592, 256>>>(x, pQ, pHb, 2, NN);     // h_res + BN1h stats
    k_bnfin<<<1, 128>>>(2, DDIM, 1.f/NN);
    k_bnapply<128><<<592, 256>>>(pHb, pK, g1h, B1h, 2, (size_t)NN*DDIM);  // hbn -> pK
    gemm<128,256,true >(pK, Wh1, bh1, pHmid, NN);
    gemm<256,128,false>(pHmid, Wh2, bh2, pV, NN);         // -> pV (V dead)
    k_addstats<128><<<592, 256>>>(pK, pV, pHb, 3, NN);    // hu + BN2h stats
    k_bnfin<<<1, 128>>>(3, DDIM, 1.f/NN);
    k_bnapply<128><<<592, 256>>>(pHb, out_h, g2h, B2h, 3, (size_t)NN*DDIM);

    // e path
    k_bnapply<64><<<592, 256>>>(pEres, pEbn, g1e, B1e, 0, (size_t)NE*EDIM);
    gemm<64,128,true >(pEbn, We1, be1, pBig, NE);         // Pe dead, reuse
    gemm<128,64,false>(pBig, We2, be2, pEres, NE);        // eres dead, reuse
    k_addstats<64><<<1024, 256>>>(pEbn, pEres, pEres, 1, NE);   // eu (in place)
    k_bnfin<<<1, 128>>>(1, EDIM, 1.f/NE);
    k_bnapply<64><<<592, 256>>>(pEres, out_e, g2e, B2e, 1, (size_t)NE*EDIM);
}

// round 8
// speedup vs baseline: 1.1485x; 1.1485x over previous
#include <cuda_runtime.h>
#include <math.h>

#define NN 30000
#define NE 480000
#define DDIM 128
#define EDIM 64
#define NH 8

// ---- scratch (__device__ globals; allocation is forbidden) ----
__device__ float g_Q[NN*DDIM], g_K[NN*DDIM], g_V[NN*DDIM];
__device__ float g_big[NE*DDIM];                 // Pe, later e-FFN mid
__device__ float g_sc[NE*NH], g_z[NN*NH];
__device__ float g_hattn[NN*DDIM];
__device__ float g_hb[NN*DDIM];
__device__ float g_hmid[NN*2*DDIM];
__device__ float g_eres[NE*EDIM], g_ebn[NE*EDIM];
__device__ float g_Wc[NH*EDIM], g_bc[EDIM];
__device__ float g_S[4][DDIM], g_Qs[4][DDIM], g_mean[4][DDIM], g_rstd[4][DDIM];
// stat slots: 0=BN1e 1=BN2e 2=BN1h 3=BN2h

__global__ void k_init() {
    int t = blockIdx.x*blockDim.x + threadIdx.x, st = gridDim.x*blockDim.x;
    for (int i = t; i < NN*DDIM; i += st) g_hattn[i] = 0.f;
    for (int i = t; i < NN*NH;  i += st) g_z[i] = 0.f;
    if (t < 4*DDIM) { (&g_S[0][0])[t] = 0.f; (&g_Qs[0][0])[t] = 0.f; }
}

// fold Wc = W_ep @ W_Oe, bc = b_ep @ W_Oe + b_Oe
__global__ void k_fold(const float* __restrict__ Wep, const float* __restrict__ bep,
                       const float* __restrict__ WOe, const float* __restrict__ bOe) {
    int t = threadIdx.x;                 // 512 threads
    int h = t >> 6, j = t & 63;
    float a = 0.f;
    for (int k = 0; k < EDIM; k++) a += Wep[h*EDIM + k] * WOe[k*EDIM + j];
    g_Wc[t] = a;
    if (t < EDIM) {
        float b = bOe[t];
        for (int k = 0; k < EDIM; k++) b += bep[k] * WOe[k*EDIM + t];
        g_bc[t] = b;
    }
}

// ---------------------------------------------------------------------------
// Weight-stationary GEMM with fused BN prologue (on input rows) and fused
// residual (+optional BN on residual) + BN-stats epilogue.
// out[M,DOUT] = act( (bn_in? BN(in):in) @ W + bias ) [+ resid or BN(resid)]
// ---------------------------------------------------------------------------
template<int DIN,int DOUT,int RPW,bool RELU,bool INBN,bool EPIRES,bool RESBN,int THREADS>
__global__ void k_gemm(const float* __restrict__ in, const float* __restrict__ W,
                       const float* __restrict__ bias, float* __restrict__ out, int M,
                       const float* __restrict__ gaIn, const float* __restrict__ beIn,
                       int slotIn,
                       const float* __restrict__ resid, const float* __restrict__ gaR,
                       const float* __restrict__ beR, int slotR, int statSlot)
{
    constexpr bool V2 = (DOUT == 64);
    constexpr int G = V2 ? 1 : DOUT/128;
    static_assert(!EPIRES || G == 1, "epilogue stats only for G==1");
    extern __shared__ float sm[];
    float* Ws  = sm;                       // DIN*DOUT
    float* scIn = Ws + DIN*DOUT;           // DIN
    float* shIn = scIn + DIN;              // DIN
    float* scR  = shIn + DIN;              // DOUT
    float* shR  = scR + DOUT;              // DOUT
    float* rows = shR + DOUT;
    const int tid = threadIdx.x, l = tid & 31, wid = tid >> 5;
    constexpr int NW = THREADS/32;
    for (int i = tid; i < DIN*DOUT/4; i += THREADS)
        ((float4*)Ws)[i] = ((const float4*)W)[i];
    if (INBN)
        for (int c = tid; c < DIN; c += THREADS) {
            float s = gaIn[c] * g_rstd[slotIn][c];
            scIn[c] = s; shIn[c] = beIn[c] - g_mean[slotIn][c]*s;
        }
    if (RESBN)
        for (int c = tid; c < DOUT; c += THREADS) {
            float s = gaR[c] * g_rstd[slotR][c];
            scR[c] = s; shR[c] = beR[c] - g_mean[slotR][c]*s;
        }
    __syncthreads();
    float* mr = rows + wid*RPW*DIN;

    float sA[4] = {0.f,0.f,0.f,0.f}, qA[4] = {0.f,0.f,0.f,0.f};
    const int nt = M / RPW;
    for (int t = blockIdx.x*NW + wid; t < nt; t += gridDim.x*NW) {
        const int r0 = t*RPW;
#pragma unroll
        for (int j = 0; j < RPW; j++) {
            const float4* src = (const float4*)(in + (size_t)(r0+j)*DIN);
            for (int i = l; i < DIN/4; i += 32) {
                float4 v = src[i];
                if (INBN) {
                    float4 s4 = ((float4*)scIn)[i], h4 = ((float4*)shIn)[i];
                    v.x = v.x*s4.x + h4.x; v.y = v.y*s4.y + h4.y;
                    v.z = v.z*s4.z + h4.z; v.w = v.w*s4.w + h4.w;
                }
                ((float4*)(mr + j*DIN))[i] = v;
            }
        }
        __syncwarp();
        if constexpr (!V2) {
            float4 acc[RPW][G];
#pragma unroll
            for (int j = 0; j < RPW; j++)
#pragma unroll
                for (int g = 0; g < G; g++)
                    acc[j][g] = bias ? ((const float4*)bias)[l + 32*g]
                                     : make_float4(0.f,0.f,0.f,0.f);
#pragma unroll 2
            for (int k4 = 0; k4 < DIN/4; k4++) {
                float4 a4[RPW];
#pragma unroll
                for (int j = 0; j < RPW; j++) a4[j] = ((float4*)(mr + j*DIN))[k4];
#pragma unroll
                for (int kk = 0; kk < 4; kk++) {
                    float4 w[G];
#pragma unroll
                    for (int g = 0; g < G; g++)
                        w[g] = ((float4*)(Ws + (k4*4+kk)*DOUT))[l + 32*g];
#pragma unroll
                    for (int j = 0; j < RPW; j++) {
                        float a = (&a4[j].x)[kk];
#pragma unroll
                        for (int g = 0; g < G; g++) {
                            acc[j][g].x += a*w[g].x; acc[j][g].y += a*w[g].y;
                            acc[j][g].z += a*w[g].z; acc[j][g].w += a*w[g].w;
                        }
                    }
                }
            }
#pragma unroll
            for (int j = 0; j < RPW; j++)
#pragma unroll
                for (int g = 0; g < G; g++) {
                    float4 v = acc[j][g];
                    if (RELU) { v.x=fmaxf(v.x,0.f); v.y=fmaxf(v.y,0.f);
                                v.z=fmaxf(v.z,0.f); v.w=fmaxf(v.w,0.f); }
                    if (EPIRES) {
                        float4 r = ((const float4*)(resid + (size_t)(r0+j)*DOUT))[l];
                        if (RESBN) {
                            float4 s4 = ((float4*)scR)[l], h4 = ((float4*)shR)[l];
                            r.x = r.x*s4.x + h4.x; r.y = r.y*s4.y + h4.y;
                            r.z = r.z*s4.z + h4.z; r.w = r.w*s4.w + h4.w;
                        }
                        v.x += r.x; v.y += r.y; v.z += r.z; v.w += r.w;
                        sA[0] += v.x; qA[0] += v.x*v.x; sA[1] += v.y; qA[1] += v.y*v.y;
                        sA[2] += v.z; qA[2] += v.z*v.z; sA[3] += v.w; qA[3] += v.w*v.w;
                    }
                    ((float4*)(out + (size_t)(r0+j)*DOUT))[l + 32*g] = v;
                }
        } else {
            float2 acc[RPW];
            float2 b2 = bias ? ((const float2*)bias)[l] : make_float2(0.f,0.f);
#pragma unroll
            for (int j = 0; j < RPW; j++) acc[j] = b2;
#pragma unroll 2
            for (int k4 = 0; k4 < DIN/4; k4++) {
                float4 a4[RPW];
#pragma unroll
                for (int j = 0; j < RPW; j++) a4[j] = ((float4*)(mr + j*DIN))[k4];
#pragma unroll
                for (int kk = 0; kk < 4; kk++) {
                    float2 w = ((float2*)(Ws + (k4*4+kk)*DOUT))[l];
#pragma unroll
                    for (int j = 0; j < RPW; j++) {
                        float a = (&a4[j].x)[kk];
                        acc[j].x += a*w.x; acc[j].y += a*w.y;
                    }
                }
            }
#pragma unroll
            for (int j = 0; j < RPW; j++) {
                float2 v = acc[j];
                if (RELU) { v.x = fmaxf(v.x,0.f); v.y = fmaxf(v.y,0.f); }
                if (EPIRES) {
                    float2 r = ((const float2*)(resid + (size_t)(r0+j)*DOUT))[l];
                    if (RESBN) {
                        float2 s2 = ((float2*)scR)[l], h2 = ((float2*)shR)[l];
                        r.x = r.x*s2.x + h2.x; r.y = r.y*s2.y + h2.y;
                    }
                    v.x += r.x; v.y += r.y;
                    sA[0] += v.x; qA[0] += v.x*v.x; sA[1] += v.y; qA[1] += v.y*v.y;
                }
                ((float2*)(out + (size_t)(r0+j)*DOUT))[l] = v;
            }
        }
        __syncwarp();
    }
    if constexpr (EPIRES) {
        if constexpr (V2) {
            atomicAdd(&g_S[statSlot][2*l],   sA[0]); atomicAdd(&g_S[statSlot][2*l+1], sA[1]);
            atomicAdd(&g_Qs[statSlot][2*l],  qA[0]); atomicAdd(&g_Qs[statSlot][2*l+1],qA[1]);
        } else {
#pragma unroll
            for (int i = 0; i < 4; i++) {
                atomicAdd(&g_S[statSlot][4*l+i],  sA[i]);
                atomicAdd(&g_Qs[statSlot][4*l+i], qA[i]);
            }
        }
    }
}

template<int DIN,int DOUT,int RPW,bool RELU,bool INBN,bool EPIRES,bool RESBN,int THREADS>
static void gemm(int grid, const float* in, const float* W, const float* bias,
                 float* out, int M,
                 const float* gaIn = nullptr, const float* beIn = nullptr, int slotIn = 0,
                 const float* resid = nullptr, const float* gaR = nullptr,
                 const float* beR = nullptr, int slotR = 0, int statSlot = 0)
{
    auto kfn = k_gemm<DIN,DOUT,RPW,RELU,INBN,EPIRES,RESBN,THREADS>;
    size_t sh = (size_t)(DIN*DOUT + 2*DIN + 2*DOUT + (THREADS/32)*RPW*DIN)*sizeof(float);
    cudaFuncSetAttribute(kfn, cudaFuncAttributeMaxDynamicSharedMemorySize, (int)sh);
    kfn<<<grid, THREADS, sh>>>(in, W, bias, out, M, gaIn, beIn, slotIn,
                               resid, gaR, beR, slotR, statSlot);
}

// per-edge: score, exp+clip, z scatter, and fused e_lin + residual + BN1e stats
__global__ void k_score(const int* __restrict__ ei, const float* __restrict__ ea) {
    const int tid = threadIdx.x, l = tid & 31;
    int gw = (blockIdx.x*blockDim.x + tid) >> 5, tot = (gridDim.x*blockDim.x) >> 5;
    float2 w[NH];
#pragma unroll
    for (int h = 0; h < NH; h++) w[h] = ((const float2*)(g_Wc + h*EDIM))[l];
    float2 bc = ((const float2*)g_bc)[l];
    float s0 = 0.f, s1 = 0.f, q0 = 0.f, q1 = 0.f;
    for (int e = gw; e < NE; e += tot) {
        int s = ei[e], d = ei[NE + e];
        float4 q = ((const float4*)g_Q)[(size_t)d*32 + l];
        float4 k = ((const float4*)g_K)[(size_t)s*32 + l];
        float4 p = ((const float4*)g_big)[(size_t)e*32 + l];
        float sc = q.x*k.x*p.x + q.y*k.y*p.y + q.z*k.z*p.z + q.w*k.w*p.w;
        sc += __shfl_xor_sync(0xffffffffu, sc, 1);
        sc += __shfl_xor_sync(0xffffffffu, sc, 2);
        sc *= 0.25f;                                   // 1/sqrt(16)
        if ((l & 3) == 0) {
            float ex = __expf(fminf(fmaxf(sc, -5.f), 5.f));
            g_sc[(size_t)e*NH + (l >> 2)] = ex;
            atomicAdd(&g_z[(size_t)d*NH + (l >> 2)], ex);
        }
        float2 acc = bc;
#pragma unroll
        for (int h = 0; h < NH; h++) {
            float sv = __shfl_sync(0xffffffffu, sc, h*4);
            acc.x += sv*w[h].x; acc.y += sv*w[h].y;
        }
        float2 eav = ((const float2*)ea)[(size_t)e*32 + l];
        acc.x += eav.x; acc.y += eav.y;
        ((float2*)g_eres)[(size_t)e*32 + l] = acc;
        s0 += acc.x; q0 += acc.x*acc.x; s1 += acc.y; q1 += acc.y*acc.y;
    }
    atomicAdd(&g_S[0][2*l], s0);   atomicAdd(&g_S[0][2*l+1], s1);
    atomicAdd(&g_Qs[0][2*l], q0);  atomicAdd(&g_Qs[0][2*l+1], q1);
}

// per-edge: alpha = sc/(z+eps); hattn[dst] += V[src]*alpha  (vector RED)
__global__ void k_alpha(const int* __restrict__ ei) {
    const int tid = threadIdx.x, l = tid & 31;
    int gw = (blockIdx.x*blockDim.x + tid) >> 5, tot = (gridDim.x*blockDim.x) >> 5;
    for (int e = gw; e < NE; e += tot) {
        int s = ei[e], d = ei[NE + e];
        int h = l >> 2;
        float a = g_sc[(size_t)e*NH + h] / (g_z[(size_t)d*NH + h] + 1e-6f);
        float4 v = ((const float4*)g_V)[(size_t)s*32 + l];
        atomicAdd(((float4*)(g_hattn + (size_t)d*DDIM)) + l,
                  make_float4(v.x*a, v.y*a, v.z*a, v.w*a));
    }
}

__global__ void k_bnfin(int slot, int C, float invn) {
    int i = threadIdx.x;
    if (i < C) {
        float mu = g_S[slot][i] * invn;
        float var = g_Qs[slot][i] * invn - mu*mu;
        g_mean[slot][i] = mu;
        g_rstd[slot][i] = rsqrtf(var + 1e-5f);
    }
}

template<int C>
__global__ void k_bnapply(const float* __restrict__ in, float* __restrict__ out,
                          const float* __restrict__ ga, const float* __restrict__ be,
                          int slot, size_t total) {
    size_t i0 = (size_t)blockIdx.x*blockDim.x + threadIdx.x;
    size_t st = (size_t)gridDim.x*blockDim.x;
    int c = (int)(i0 & (C - 1));
    float sc = ga[c] * g_rstd[slot][c];
    float sh = be[c] - g_mean[slot][c] * sc;
    for (size_t i = i0; i < total; i += st) out[i] = in[i]*sc + sh;
}

extern "C" void kernel_launch(void* const* d_in, const int* in_sizes, int n_in,
                              void* d_out, int out_size) {
    const float* x   = (const float*)d_in[0];
    const int*   ei  = (const int*)  d_in[1];
    const float* ea  = (const float*)d_in[2];
    const float *Wq = (const float*)d_in[3], *Wk = (const float*)d_in[4];
    const float *Wv = (const float*)d_in[5], *We = (const float*)d_in[6];
    const float *WOh = (const float*)d_in[7],  *bOh = (const float*)d_in[8];
    const float *Wep = (const float*)d_in[9],  *bep = (const float*)d_in[10];
    const float *WOe = (const float*)d_in[11], *bOe = (const float*)d_in[12];
    const float *Wh1 = (const float*)d_in[13], *bh1 = (const float*)d_in[14];
    const float *Wh2 = (const float*)d_in[15], *bh2 = (const float*)d_in[16];
    const float *We1 = (const float*)d_in[17], *be1 = (const float*)d_in[18];
    const float *We2 = (const float*)d_in[19], *be2 = (const float*)d_in[20];
    const float *g1h = (const float*)d_in[21], *B1h = (const float*)d_in[22];
    const float *g1e = (const float*)d_in[23], *B1e = (const float*)d_in[24];
    const float *g2h = (const float*)d_in[25], *B2h = (const float*)d_in[26];
    const float *g2e = (const float*)d_in[27], *B2e = (const float*)d_in[28];
    float* out_h = (float*)d_out;
    float* out_e = out_h + (size_t)NN*DDIM;

    float *pQ, *pK, *pV, *pBig, *pHat, *pHb, *pHmid, *pEres, *pEbn;
    cudaGetSymbolAddress((void**)&pQ, g_Q);
    cudaGetSymbolAddress((void**)&pK, g_K);
    cudaGetSymbolAddress((void**)&pV, g_V);
    cudaGetSymbolAddress((void**)&pBig, g_big);
    cudaGetSymbolAddress((void**)&pHat, g_hattn);
    cudaGetSymbolAddress((void**)&pHb, g_hb);
    cudaGetSymbolAddress((void**)&pHmid, g_hmid);
    cudaGetSymbolAddress((void**)&pEres, g_eres);
    cudaGetSymbolAddress((void**)&pEbn, g_ebn);

    k_init<<<592, 256>>>();
    k_fold<<<1, 512>>>(Wep, bep, WOe, bOe);

    // attention projections
    gemm<128,128,8,false,false,false,false,256>(296, x, Wq, nullptr, pQ, NN);
    gemm<128,128,8,false,false,false,false,256>(296, x, Wk, nullptr, pK, NN);
    gemm<128,128,8,false,false,false,false,256>(296, x, Wv, nullptr, pV, NN);
    gemm< 64,128,8,false,false,false,false,256>(296, ea, We, nullptr, pBig, NE); // Pe

    // score + softmax denom + fused e_lin/residual/BN1e stats
    k_score<<<592, 256>>>(ei, ea);
    k_bnfin<<<1, 128>>>(0, EDIM, 1.f/NE);
    k_alpha<<<592, 256>>>(ei);

    // h path: Oh proj + residual(x) + BN1h stats fused
    gemm<128,128,8,false,false,true,false,256>(296, pHat, WOh, bOh, pHb, NN,
        nullptr, nullptr, 0, x, nullptr, nullptr, 0, 2);
    k_bnfin<<<1, 128>>>(2, DDIM, 1.f/NN);
    // FFN1: BN1h applied inline on input rows
    gemm<128,256,4,true,true,false,false,512>(148, pHb, Wh1, bh1, pHmid, NN,
        g1h, B1h, 2);
    // FFN2: residual = BN1h(hb) recomputed inline; BN2h stats fused
    gemm<256,128,4,false,false,true,true,512>(148, pHmid, Wh2, bh2, pQ, NN,
        nullptr, nullptr, 0, pHb, g1h, B1h, 2, 3);
    k_bnfin<<<1, 128>>>(3, DDIM, 1.f/NN);
    k_bnapply<128><<<592, 256>>>(pQ, out_h, g2h, B2h, 3, (size_t)NN*DDIM);

    // e path: FFN1 with BN1e inline on eres
    gemm< 64,128,8,true,true,false,false,256>(296, pEres, We1, be1, pBig, NE,
        g1e, B1e, 0);
    // FFN2: residual = BN1e(eres) inline; BN2e stats fused
    gemm<128, 64,8,false,false,true,true,256>(296, pBig, We2, be2, pEbn, NE,
        nullptr, nullptr, 0, pEres, g1e, B1e, 0, 1);
    k_bnfin<<<1, 128>>>(1, EDIM, 1.f/NE);
    k_bnapply<64><<<592, 256>>>(pEbn, out_e, g2e, B2e, 1, (size_t)NE*EDIM);
}

// round 11
// speedup vs baseline: 1.3048x; 1.1361x over previous
#include <cuda_runtime.h>
#include <math.h>
#include <stdint.h>

#define NN 30000
#define NE 480000
#define DDIM 128
#define EDIM 64
#define NH 8

// ---- scratch (__device__ globals; allocation is forbidden) ----
__device__ float g_Q[NN*DDIM], g_K[NN*DDIM], g_V[NN*DDIM];
__device__ float g_big[NE*DDIM];                 // Pe, later e-FFN mid
__device__ float g_sc[NE*NH], g_z[NN*NH];
__device__ float g_hattn[NN*DDIM];
__device__ float g_hb[NN*DDIM];
__device__ float g_hmid[NN*2*DDIM];
__device__ float g_eres[NE*EDIM], g_ebn[NE*EDIM];
__device__ float g_Wc[NH*EDIM], g_bc[EDIM];
__device__ float g_S[4][DDIM], g_Qs[4][DDIM], g_mean[4][DDIM], g_rstd[4][DDIM];
// stat slots: 0=BN1e 1=BN2e 2=BN1h 3=BN2h

__device__ __forceinline__ float f2tf(float x) {
    unsigned int u; asm("cvt.rna.tf32.f32 %0, %1;" : "=r"(u) : "f"(x));
    return __uint_as_float(u);
}
__device__ __forceinline__ void mma8(float* d, const unsigned int* a,
                                     unsigned int b0, unsigned int b1) {
    asm("mma.sync.aligned.m16n8k8.row.col.f32.tf32.tf32.f32 "
        "{%0,%1,%2,%3},{%4,%5,%6,%7},{%8,%9},{%0,%1,%2,%3};"
        : "+f"(d[0]), "+f"(d[1]), "+f"(d[2]), "+f"(d[3])
        : "r"(a[0]), "r"(a[1]), "r"(a[2]), "r"(a[3]), "r"(b0), "r"(b1));
}

__global__ void k_init() {
    int t = blockIdx.x*blockDim.x + threadIdx.x, st = gridDim.x*blockDim.x;
    for (int i = t; i < NN*DDIM; i += st) g_hattn[i] = 0.f;
    for (int i = t; i < NN*NH;  i += st) g_z[i] = 0.f;
    if (t < 4*DDIM) { (&g_S[0][0])[t] = 0.f; (&g_Qs[0][0])[t] = 0.f; }
}

// fold Wc = W_ep @ W_Oe, bc = b_ep @ W_Oe + b_Oe
__global__ void k_fold(const float* __restrict__ Wep, const float* __restrict__ bep,
                       const float* __restrict__ WOe, const float* __restrict__ bOe) {
    int t = threadIdx.x;                 // 512 threads
    int h = t >> 6, j = t & 63;
    float a = 0.f;
    for (int k = 0; k < EDIM; k++) a += Wep[h*EDIM + k] * WOe[k*EDIM + j];
    g_Wc[t] = a;
    if (t < EDIM) {
        float b = bOe[t];
        for (int k = 0; k < EDIM; k++) b += bep[k] * WOe[k*EDIM + t];
        g_bc[t] = b;
    }
}

// ---------------------------------------------------------------------------
// Tensor-core (tf32, 3xTF32-compensated) weight-stationary GEMM.
// Block handles output columns [blockIdx.y*NT*8, +NT*8). Warp computes an
// RPW x NT*8 tile with mma.m16n8k8. Fusions: INBN on input rows, bias, ReLU,
// residual (+BN on residual) + BN-stat accumulation in epilogue.
// ---------------------------------------------------------------------------
template<int DIN,int NT,int RPW,bool RELU,bool INBN,bool EPIRES,bool RESBN,int THREADS>
__global__ void k_tgemm(const float* __restrict__ in, const float* __restrict__ W,
                        const float* __restrict__ bias, float* __restrict__ out,
                        int M, int WLD, int LD,
                        const float* __restrict__ gaIn, const float* __restrict__ beIn,
                        int slotIn,
                        const float* __restrict__ resid, const float* __restrict__ gaR,
                        const float* __restrict__ beR, int slotR, int statSlot)
{
    constexpr int MF = RPW/16;             // m16 fragments per strip
    constexpr int NW = THREADS/32;
    constexpr int KS = DIN/8;              // k8 steps
    extern __shared__ float sm[];
    float* Wp    = sm;                     // NT*KS*128 floats (frag-packed hi/lo)
    float* scIn  = Wp + NT*KS*128;         // DIN
    float* shIn  = scIn + DIN;             // DIN
    float* biasS = shIn + DIN;             // NT*8
    float* scR   = biasS + NT*8;           // NT*8
    float* shR   = scR + NT*8;             // NT*8
    float* sS    = shR + NT*8;             // NT*8 stat reduce
    float* sQ    = sS + NT*8;              // NT*8
    const int tid = threadIdx.x, l = tid & 31, wid = tid >> 5;
    const int n0 = blockIdx.y * NT * 8;

    // pack W tile: for (tile t, step s, lane): {hi(k,n), hi(k+4,n), lo(k,n), lo(k+4,n)}
    for (int i = tid; i < NT*KS*32; i += THREADS) {
        int ll = i & 31, si = (i >> 5) % KS, ti = (i >> 5) / KS;
        int k = si*8 + (ll & 3), n = n0 + ti*8 + (ll >> 2);
        float w0 = W[(size_t)k*WLD + n];
        float w1 = W[(size_t)(k+4)*WLD + n];
        float h0 = f2tf(w0), h1 = f2tf(w1);
        ((float4*)Wp)[i] = make_float4(h0, h1, f2tf(w0 - h0), f2tf(w1 - h1));
    }
    for (int c = tid; c < NT*8; c += THREADS) {
        biasS[c] = bias ? bias[n0 + c] : 0.f;
        sS[c] = 0.f; sQ[c] = 0.f;
    }
    if (INBN)
        for (int c = tid; c < DIN; c += THREADS) {
            float s = gaIn[c] * g_rstd[slotIn][c];
            scIn[c] = s; shIn[c] = beIn[c] - g_mean[slotIn][c]*s;
        }
    if (RESBN)
        for (int c = tid; c < NT*8; c += THREADS) {
            float s = gaR[n0+c] * g_rstd[slotR][n0+c];
            scR[c] = s; shR[c] = beR[n0+c] - g_mean[slotR][n0+c]*s;
        }
    __syncthreads();

    float sA[NT][2], qA[NT][2];
    if (EPIRES) {
#pragma unroll
        for (int t = 0; t < NT; t++) { sA[t][0]=sA[t][1]=qA[t][0]=qA[t][1]=0.f; }
    }

    const int nstrip = M / RPW;
    for (int strip = blockIdx.x*NW + wid; strip < nstrip; strip += gridDim.x*NW) {
        const int r0 = strip * RPW;
        float C[NT][MF*4];
#pragma unroll
        for (int t = 0; t < NT; t++) {
            float b0 = biasS[t*8 + (l&3)*2], b1 = biasS[t*8 + (l&3)*2 + 1];
#pragma unroll
            for (int f = 0; f < MF; f++) {
                C[t][f*4+0] = b0; C[t][f*4+1] = b1;
                C[t][f*4+2] = b0; C[t][f*4+3] = b1;
            }
        }
        const float* aBase = in + (size_t)(r0 + (l>>2))*DIN + (l&3);
#define LOADA(S, DST)                                                      \
        {                                                                  \
            _Pragma("unroll")                                              \
            for (int f = 0; f < MF; f++) {                                 \
                const float* p = aBase + (size_t)f*16*DIN + (S)*8;         \
                DST[f][0] = p[0];                                          \
                DST[f][1] = p[(size_t)8*DIN];                              \
                DST[f][2] = p[4];                                          \
                DST[f][3] = p[(size_t)8*DIN + 4];                          \
            }                                                              \
        }
        float raw[MF][4], rawN[MF][4];
        LOADA(0, raw);
#pragma unroll 1
        for (int s = 0; s < KS; s++) {
            if (s + 1 < KS) LOADA(s+1, rawN);
            float sc0, sh0, sc1, sh1;
            if (INBN) {
                sc0 = scIn[s*8 + (l&3)];     sh0 = shIn[s*8 + (l&3)];
                sc1 = scIn[s*8 + 4 + (l&3)]; sh1 = shIn[s*8 + 4 + (l&3)];
            }
            unsigned int ahi[MF][4], alo[MF][4];
#pragma unroll
            for (int f = 0; f < MF; f++)
#pragma unroll
                for (int j = 0; j < 4; j++) {
                    float a = raw[f][j];
                    if (INBN) a = a * ((j >> 1) ? sc1 : sc0) + ((j >> 1) ? sh1 : sh0);
                    float h = f2tf(a);
                    ahi[f][j] = __float_as_uint(h);
                    alo[f][j] = __float_as_uint(f2tf(a - h));
                }
#pragma unroll
            for (int t = 0; t < NT; t++) {
                float4 pk = ((const float4*)Wp)[(t*KS + s)*32 + l];
                unsigned int bh0 = __float_as_uint(pk.x), bh1 = __float_as_uint(pk.y);
                unsigned int bl0 = __float_as_uint(pk.z), bl1 = __float_as_uint(pk.w);
#pragma unroll
                for (int f = 0; f < MF; f++) {
                    mma8(&C[t][f*4], ahi[f], bh0, bh1);
                    mma8(&C[t][f*4], ahi[f], bl0, bl1);
                    mma8(&C[t][f*4], alo[f], bh0, bh1);
                }
            }
#pragma unroll
            for (int f = 0; f < MF; f++)
#pragma unroll
                for (int j = 0; j < 4; j++) raw[f][j] = rawN[f][j];
        }
#undef LOADA
        // epilogue
#pragma unroll
        for (int t = 0; t < NT; t++) {
            const int col = n0 + t*8 + (l&3)*2;
#pragma unroll
            for (int f = 0; f < MF; f++)
#pragma unroll
                for (int half = 0; half < 2; half++) {
                    int row = r0 + f*16 + (l>>2) + half*8;
                    float v0 = C[t][f*4 + half*2], v1 = C[t][f*4 + half*2 + 1];
                    if (RELU) { v0 = fmaxf(v0, 0.f); v1 = fmaxf(v1, 0.f); }
                    if (EPIRES) {
                        float2 r2 = *(const float2*)(resid + (size_t)row*LD + col);
                        if (RESBN) {
                            r2.x = r2.x*scR[t*8+(l&3)*2]   + shR[t*8+(l&3)*2];
                            r2.y = r2.y*scR[t*8+(l&3)*2+1] + shR[t*8+(l&3)*2+1];
                        }
                        v0 += r2.x; v1 += r2.y;
                        sA[t][0] += v0; qA[t][0] += v0*v0;
                        sA[t][1] += v1; qA[t][1] += v1*v1;
                    }
                    *(float2*)(out + (size_t)row*LD + col) = make_float2(v0, v1);
                }
        }
    }
    if (EPIRES) {
#pragma unroll
        for (int t = 0; t < NT; t++)
#pragma unroll
            for (int j = 0; j < 2; j++) {
                float s = sA[t][j], q = qA[t][j];
                s += __shfl_xor_sync(0xffffffffu, s, 4);
                q += __shfl_xor_sync(0xffffffffu, q, 4);
                s += __shfl_xor_sync(0xffffffffu, s, 8);
                q += __shfl_xor_sync(0xffffffffu, q, 8);
                s += __shfl_xor_sync(0xffffffffu, s, 16);
                q += __shfl_xor_sync(0xffffffffu, q, 16);
                if (l < 4) {
                    atomicAdd(&sS[t*8 + l*2 + j], s);
                    atomicAdd(&sQ[t*8 + l*2 + j], q);
                }
            }
        __syncthreads();
        for (int c = tid; c < NT*8; c += THREADS) {
            atomicAdd(&g_S[statSlot][n0 + c],  sS[c]);
            atomicAdd(&g_Qs[statSlot][n0 + c], sQ[c]);
        }
    }
}

template<int DIN,int NT,int RPW,bool RELU,bool INBN,bool EPIRES,bool RESBN,int THREADS>
static void tgemm(dim3 grid, const float* in, const float* W, const float* bias,
                  float* out, int M, int WLD, int LD,
                  const float* gaIn = nullptr, const float* beIn = nullptr, int slotIn = 0,
                  const float* resid = nullptr, const float* gaR = nullptr,
                  const float* beR = nullptr, int slotR = 0, int statSlot = 0)
{
    auto kfn = k_tgemm<DIN,NT,RPW,RELU,INBN,EPIRES,RESBN,THREADS>;
    size_t sh = (size_t)(NT*(DIN/8)*128 + 2*DIN + 5*NT*8) * sizeof(float);
    cudaFuncSetAttribute(kfn, cudaFuncAttributeMaxDynamicSharedMemorySize, (int)sh);
    kfn<<<grid, THREADS, sh>>>(in, W, bias, out, M, WLD, LD, gaIn, beIn, slotIn,
                               resid, gaR, beR, slotR, statSlot);
}

// per-edge: score, exp+clip, z scatter, and fused e_lin + residual + BN1e stats
__global__ void k_score(const int* __restrict__ ei, const float* __restrict__ ea) {
    const int tid = threadIdx.x, l = tid & 31;
    int gw = (blockIdx.x*blockDim.x + tid) >> 5, tot = (gridDim.x*blockDim.x) >> 5;
    float2 w[NH];
#pragma unroll
    for (int h = 0; h < NH; h++) w[h] = ((const float2*)(g_Wc + h*EDIM))[l];
    float2 bc = ((const float2*)g_bc)[l];
    float s0 = 0.f, s1 = 0.f, q0 = 0.f, q1 = 0.f;
    for (int e = gw; e < NE; e += tot) {
        int s = ei[e], d = ei[NE + e];
        float4 q = ((const float4*)g_Q)[(size_t)d*32 + l];
        float4 k = ((const float4*)g_K)[(size_t)s*32 + l];
        float4 p = ((const float4*)g_big)[(size_t)e*32 + l];
        float sc = q.x*k.x*p.x + q.y*k.y*p.y + q.z*k.z*p.z + q.w*k.w*p.w;
        sc += __shfl_xor_sync(0xffffffffu, sc, 1);
        sc += __shfl_xor_sync(0xffffffffu, sc, 2);
        sc *= 0.25f;                                   // 1/sqrt(16)
        if ((l & 3) == 0) {
            float ex = __expf(fminf(fmaxf(sc, -5.f), 5.f));
            g_sc[(size_t)e*NH + (l >> 2)] = ex;
            atomicAdd(&g_z[(size_t)d*NH + (l >> 2)], ex);
        }
        float2 acc = bc;
#pragma unroll
        for (int h = 0; h < NH; h++) {
            float sv = __shfl_sync(0xffffffffu, sc, h*4);
            acc.x += sv*w[h].x; acc.y += sv*w[h].y;
        }
        float2 eav = ((const float2*)ea)[(size_t)e*32 + l];
        acc.x += eav.x; acc.y += eav.y;
        ((float2*)g_eres)[(size_t)e*32 + l] = acc;
        s0 += acc.x; q0 += acc.x*acc.x; s1 += acc.y; q1 += acc.y*acc.y;
    }
    atomicAdd(&g_S[0][2*l], s0);   atomicAdd(&g_S[0][2*l+1], s1);
    atomicAdd(&g_Qs[0][2*l], q0);  atomicAdd(&g_Qs[0][2*l+1], q1);
}

// per-edge: alpha = sc/(z+eps); hattn[dst] += V[src]*alpha  (vector RED)
__global__ void k_alpha(const int* __restrict__ ei) {
    const int tid = threadIdx.x, l = tid & 31;
    int gw = (blockIdx.x*blockDim.x + tid) >> 5, tot = (gridDim.x*blockDim.x) >> 5;
    for (int e = gw; e < NE; e += tot) {
        int s = ei[e], d = ei[NE + e];
        int h = l >> 2;
        float a = g_sc[(size_t)e*NH + h] / (g_z[(size_t)d*NH + h] + 1e-6f);
        float4 v = ((const float4*)g_V)[(size_t)s*32 + l];
        atomicAdd(((float4*)(g_hattn + (size_t)d*DDIM)) + l,
                  make_float4(v.x*a, v.y*a, v.z*a, v.w*a));
    }
}

__global__ void k_bnfin(int slot, int C, float invn) {
    int i = threadIdx.x;
    if (i < C) {
        float mu = g_S[slot][i] * invn;
        float var = g_Qs[slot][i] * invn - mu*mu;
        g_mean[slot][i] = mu;
        g_rstd[slot][i] = rsqrtf(var + 1e-5f);
    }
}

template<int C>
__global__ void k_bnapply(const float* __restrict__ in, float* __restrict__ out,
                          const float* __restrict__ ga, const float* __restrict__ be,
                          int slot, size_t total) {
    size_t i0 = (size_t)blockIdx.x*blockDim.x + threadIdx.x;
    size_t st = (size_t)gridDim.x*blockDim.x;
    int c = (int)(i0 & (C - 1));
    float sc = ga[c] * g_rstd[slot][c];
    float sh = be[c] - g_mean[slot][c] * sc;
    for (size_t i = i0; i < total; i += st) out[i] = in[i]*sc + sh;
}

extern "C" void kernel_launch(void* const* d_in, const int* in_sizes, int n_in,
                              void* d_out, int out_size) {
    const float* x   = (const float*)d_in[0];
    const int*   ei  = (const int*)  d_in[1];
    const float* ea  = (const float*)d_in[2];
    const float *Wq = (const float*)d_in[3], *Wk = (const float*)d_in[4];
    const float *Wv = (const float*)d_in[5], *We = (const float*)d_in[6];
    const float *WOh = (const float*)d_in[7],  *bOh = (const float*)d_in[8];
    const float *Wep = (const float*)d_in[9],  *bep = (const float*)d_in[10];
    const float *WOe = (const float*)d_in[11], *bOe = (const float*)d_in[12];
    const float *Wh1 = (const float*)d_in[13], *bh1 = (const float*)d_in[14];
    const float *Wh2 = (const float*)d_in[15], *bh2 = (const float*)d_in[16];
    const float *We1 = (const float*)d_in[17], *be1 = (const float*)d_in[18];
    const float *We2 = (const float*)d_in[19], *be2 = (const float*)d_in[20];
    const float *g1h = (const float*)d_in[21], *B1h = (const float*)d_in[22];
    const float *g1e = (const float*)d_in[23], *B1e = (const float*)d_in[24];
    const float *g2h = (const float*)d_in[25], *B2h = (const float*)d_in[26];
    const float *g2e = (const float*)d_in[27], *B2e = (const float*)d_in[28];
    float* out_h = (float*)d_out;
    float* out_e = out_h + (size_t)NN*DDIM;

    float *pQ, *pK, *pV, *pBig, *pHat, *pHb, *pHmid, *pEres, *pEbn;
    cudaGetSymbolAddress((void**)&pQ, g_Q);
    cudaGetSymbolAddress((void**)&pK, g_K);
    cudaGetSymbolAddress((void**)&pV, g_V);
    cudaGetSymbolAddress((void**)&pBig, g_big);
    cudaGetSymbolAddress((void**)&pHat, g_hattn);
    cudaGetSymbolAddress((void**)&pHb, g_hb);
    cudaGetSymbolAddress((void**)&pHmid, g_hmid);
    cudaGetSymbolAddress((void**)&pEres, g_eres);
    cudaGetSymbolAddress((void**)&pEbn, g_ebn);

    k_init<<<592, 256>>>();
    k_fold<<<1, 512>>>(Wep, bep, WOe, bOe);

    // attention projections (tensor core)
    tgemm<128,8,16,false,false,false,false,256>(dim3(235,2), x, Wq, nullptr, pQ, NN, 128, 128);
    tgemm<128,8,16,false,false,false,false,256>(dim3(235,2), x, Wk, nullptr, pK, NN, 128, 128);
    tgemm<128,8,16,false,false,false,false,256>(dim3(235,2), x, Wv, nullptr, pV, NN, 128, 128);
    tgemm< 64,8,32,false,false,false,false,256>(dim3(296,2), ea, We, nullptr, pBig, NE, 128, 128); // Pe

    // score + softmax denom + fused e_lin/residual/BN1e stats
    k_score<<<592, 256>>>(ei, ea);
    k_bnfin<<<1, 128>>>(0, EDIM, 1.f/NE);
    k_alpha<<<592, 256>>>(ei);

    // h path: Oh proj + residual(x) + BN1h stats fused
    tgemm<128,8,16,false,false,true,false,256>(dim3(235,2), pHat, WOh, bOh, pHb, NN, 128, 128,
        nullptr, nullptr, 0, x, nullptr, nullptr, 0, 2);
    k_bnfin<<<1, 128>>>(2, DDIM, 1.f/NN);
    // FFN1: BN1h applied inline on input rows
    tgemm<128,8,16,true,true,false,false,256>(dim3(235,4), pHb, Wh1, bh1, pHmid, NN, 256, 256,
        g1h, B1h, 2);
    // FFN2: residual = BN1h(hb) recomputed inline; BN2h stats fused
    tgemm<256,8,16,false,false,true,true,256>(dim3(235,2), pHmid, Wh2, bh2, pQ, NN, 128, 128,
        nullptr, nullptr, 0, pHb, g1h, B1h, 2, 3);
    k_bnfin<<<1, 128>>>(3, DDIM, 1.f/NN);
    k_bnapply<128><<<592, 256>>>(pQ, out_h, g2h, B2h, 3, (size_t)NN*DDIM);

    // e path: FFN1 with BN1e inline on eres
    tgemm< 64,8,32,true,true,false,false,256>(dim3(296,2), pEres, We1, be1, pBig, NE, 128, 128,
        g1e, B1e, 0);
    // FFN2: residual = BN1e(eres) inline; BN2e stats fused
    tgemm<128,8,32,false,false,true,true,256>(dim3(296,1), pBig, We2, be2, pEbn, NE, 64, 64,
        nullptr, nullptr, 0, pEres, g1e, B1e, 0, 1);
    k_bnfin<<<1, 128>>>(1, EDIM, 1.f/NE);
    k_bnapply<64><<<592, 256>>>(pEbn, out_e, g2e, B2e, 1, (size_t)NE*EDIM);
}

// round 12
// speedup vs baseline: 1.5546x; 1.1914x over previous
#include <cuda_runtime.h>
#include <cuda_bf16.h>
#include <math.h>
#include <stdint.h>

#define NN 30000
#define NE 480000
#define DDIM 128
#define EDIM 64
#define NH 8

// ---- scratch (__device__ globals; allocation is forbidden) ----
__device__ float g_Q[NN*DDIM], g_K[NN*DDIM], g_V[NN*DDIM];
__device__ float g_big[NE*DDIM];                 // Pe, later e-FFN mid
__device__ float g_sc[NE*NH], g_z[NN*NH];
__device__ float g_hattn[NN*DDIM];
__device__ float g_hb[NN*DDIM];
__device__ float g_hmid[NN*2*DDIM];
__device__ float g_eres[NE*EDIM], g_ebn[NE*EDIM];
__device__ float g_Wc[NH*EDIM], g_bc[EDIM];
__device__ float g_S[4][DDIM], g_Qs[4][DDIM], g_mean[4][DDIM], g_rstd[4][DDIM];
// stat slots: 0=BN1e 1=BN2e 2=BN1h 3=BN2h

__device__ __forceinline__ void mma16(float* d, const unsigned int* a,
                                      unsigned int b0, unsigned int b1) {
    asm("mma.sync.aligned.m16n8k16.row.col.f32.bf16.bf16.f32 "
        "{%0,%1,%2,%3},{%4,%5,%6,%7},{%8,%9},{%0,%1,%2,%3};"
        : "+f"(d[0]), "+f"(d[1]), "+f"(d[2]), "+f"(d[3])
        : "r"(a[0]), "r"(a[1]), "r"(a[2]), "r"(a[3]), "r"(b0), "r"(b1));
}

// split a float2 into packed bf16x2 hi and lo (a = hi + lo + O(2^-17 a))
__device__ __forceinline__ void split2(float2 f, unsigned int& hi, unsigned int& lo) {
    __nv_bfloat162 h = __floats2bfloat162_rn(f.x, f.y);
    float2 hf = __bfloat1622float2(h);
    __nv_bfloat162 l2 = __floats2bfloat162_rn(f.x - hf.x, f.y - hf.y);
    hi = *reinterpret_cast<unsigned int*>(&h);
    lo = *reinterpret_cast<unsigned int*>(&l2);
}

__global__ void k_init() {
    int t = blockIdx.x*blockDim.x + threadIdx.x, st = gridDim.x*blockDim.x;
    for (int i = t; i < NN*DDIM; i += st) g_hattn[i] = 0.f;
    for (int i = t; i < NN*NH;  i += st) g_z[i] = 0.f;
    if (t < 4*DDIM) { (&g_S[0][0])[t] = 0.f; (&g_Qs[0][0])[t] = 0.f; }
}

// fold Wc = W_ep @ W_Oe, bc = b_ep @ W_Oe + b_Oe
__global__ void k_fold(const float* __restrict__ Wep, const float* __restrict__ bep,
                       const float* __restrict__ WOe, const float* __restrict__ bOe) {
    int t = threadIdx.x;                 // 512 threads
    int h = t >> 6, j = t & 63;
    float a = 0.f;
    for (int k = 0; k < EDIM; k++) a += Wep[h*EDIM + k] * WOe[k*EDIM + j];
    g_Wc[t] = a;
    if (t < EDIM) {
        float b = bOe[t];
        for (int k = 0; k < EDIM; k++) b += bep[k] * WOe[k*EDIM + t];
        g_bc[t] = b;
    }
}

// ---------------------------------------------------------------------------
// Tensor-core GEMM: split-bf16 (hi/lo) with 3-term compensation on
// mma.m16n8k16 — ~fp32 accuracy at half the MMA/load cost of 3xTF32 k8.
// Block handles output columns [blockIdx.y*NT*8, +NT*8). Warp computes an
// RPW x NT*8 tile. Fusions: INBN on input rows, bias, ReLU, residual
// (+BN on residual) + BN-stat accumulation in epilogue.
// ---------------------------------------------------------------------------
template<int DIN,int NT,int RPW,bool RELU,bool INBN,bool EPIRES,bool RESBN,int THREADS>
__global__ void k_tgemm(const float* __restrict__ in, const float* __restrict__ W,
                        const float* __restrict__ bias, float* __restrict__ out,
                        int M, int WLD, int LD,
                        const float* __restrict__ gaIn, const float* __restrict__ beIn,
                        int slotIn,
                        const float* __restrict__ resid, const float* __restrict__ gaR,
                        const float* __restrict__ beR, int slotR, int statSlot)
{
    constexpr int MF = RPW/16;             // m16 fragments per strip
    constexpr int NW = THREADS/32;
    constexpr int KS = DIN/16;             // k16 steps
    extern __shared__ float sm[];
    float* Wp    = sm;                     // NT*KS*128 words: uint4/lane {hi0,hi1,lo0,lo1}
    float* scIn  = Wp + NT*KS*128;         // DIN
    float* shIn  = scIn + DIN;             // DIN
    float* biasS = shIn + DIN;             // NT*8
    float* scR   = biasS + NT*8;           // NT*8
    float* shR   = scR + NT*8;             // NT*8
    float* sS    = shR + NT*8;             // NT*8 stat reduce
    float* sQ    = sS + NT*8;              // NT*8
    const int tid = threadIdx.x, l = tid & 31, wid = tid >> 5;
    const int n0 = blockIdx.y * NT * 8;

    // pack W tile: lane covers n = n0+t*8+(l>>2), k pairs (k0,k0+1) and (k0+8,k0+9)
    for (int i = tid; i < NT*KS*32; i += THREADS) {
        int ll = i & 31, si = (i >> 5) % KS, ti = (i >> 5) / KS;
        int k0 = si*16 + (ll & 3)*2, n = n0 + ti*8 + (ll >> 2);
        float2 w0 = make_float2(W[(size_t)k0*WLD + n],     W[(size_t)(k0+1)*WLD + n]);
        float2 w1 = make_float2(W[(size_t)(k0+8)*WLD + n], W[(size_t)(k0+9)*WLD + n]);
        unsigned int h0, l0, h1, l1;
        split2(w0, h0, l0); split2(w1, h1, l1);
        ((uint4*)Wp)[i] = make_uint4(h0, h1, l0, l1);
    }
    for (int c = tid; c < NT*8; c += THREADS) {
        biasS[c] = bias ? bias[n0 + c] : 0.f;
        sS[c] = 0.f; sQ[c] = 0.f;
    }
    if (INBN)
        for (int c = tid; c < DIN; c += THREADS) {
            float s = gaIn[c] * g_rstd[slotIn][c];
            scIn[c] = s; shIn[c] = beIn[c] - g_mean[slotIn][c]*s;
        }
    if (RESBN)
        for (int c = tid; c < NT*8; c += THREADS) {
            float s = gaR[n0+c] * g_rstd[slotR][n0+c];
            scR[c] = s; shR[c] = beR[n0+c] - g_mean[slotR][n0+c]*s;
        }
    __syncthreads();

    float sA[NT][2], qA[NT][2];
    if (EPIRES) {
#pragma unroll
        for (int t = 0; t < NT; t++) { sA[t][0]=sA[t][1]=qA[t][0]=qA[t][1]=0.f; }
    }

    const int nstrip = M / RPW;
    for (int strip = blockIdx.x*NW + wid; strip < nstrip; strip += gridDim.x*NW) {
        const int r0 = strip * RPW;
        float C[NT][MF*4];
#pragma unroll
        for (int t = 0; t < NT; t++) {
            float b0 = biasS[t*8 + (l&3)*2], b1 = biasS[t*8 + (l&3)*2 + 1];
#pragma unroll
            for (int f = 0; f < MF; f++) {
                C[t][f*4+0] = b0; C[t][f*4+1] = b1;
                C[t][f*4+2] = b0; C[t][f*4+3] = b1;
            }
        }
        const float* aBase = in + (size_t)(r0 + (l>>2))*DIN + (l&3)*2;
        // per step, per fragment: raw[f] = {(r,k0) , (r+8,k0) , (r,k0+8) , (r+8,k0+8)}
#define LOADA(S, DST)                                                      \
        {                                                                  \
            _Pragma("unroll")                                              \
            for (int f = 0; f < MF; f++) {                                 \
                const float* p = aBase + (size_t)f*16*DIN + (S)*16;        \
                DST[f][0] = *(const float2*)(p);                           \
                DST[f][1] = *(const float2*)(p + (size_t)8*DIN);           \
                DST[f][2] = *(const float2*)(p + 8);                       \
                DST[f][3] = *(const float2*)(p + (size_t)8*DIN + 8);       \
            }                                                              \
        }
        float2 raw[MF][4], rawN[MF][4];
        LOADA(0, raw);
#pragma unroll 1
        for (int s = 0; s < KS; s++) {
            if (s + 1 < KS) LOADA(s+1, rawN);
            float2 sc0, sh0, sc1, sh1;
            if (INBN) {
                int c0 = s*16 + (l&3)*2;
                sc0 = *(float2*)(scIn + c0);     sh0 = *(float2*)(shIn + c0);
                sc1 = *(float2*)(scIn + c0 + 8); sh1 = *(float2*)(shIn + c0 + 8);
            }
            unsigned int ahi[MF][4], alo[MF][4];
#pragma unroll
            for (int f = 0; f < MF; f++)
#pragma unroll
                for (int j = 0; j < 4; j++) {
                    float2 a = raw[f][j];
                    if (INBN) {
                        float2 s2 = (j >> 1) ? sc1 : sc0, h2 = (j >> 1) ? sh1 : sh0;
                        a.x = a.x*s2.x + h2.x; a.y = a.y*s2.y + h2.y;
                    }
                    split2(a, ahi[f][j], alo[f][j]);
                }
#pragma unroll
            for (int t = 0; t < NT; t++) {
                uint4 pk = ((const uint4*)Wp)[(t*KS + s)*32 + l];
#pragma unroll
                for (int f = 0; f < MF; f++) {
                    mma16(&C[t][f*4], ahi[f], pk.x, pk.y);
                    mma16(&C[t][f*4], ahi[f], pk.z, pk.w);
                    mma16(&C[t][f*4], alo[f], pk.x, pk.y);
                }
            }
#pragma unroll
            for (int f = 0; f < MF; f++)
#pragma unroll
                for (int j = 0; j < 4; j++) raw[f][j] = rawN[f][j];
        }
#undef LOADA
        // epilogue
#pragma unroll
        for (int t = 0; t < NT; t++) {
            const int col = n0 + t*8 + (l&3)*2;
#pragma unroll
            for (int f = 0; f < MF; f++)
#pragma unroll
                for (int half = 0; half < 2; half++) {
                    int row = r0 + f*16 + (l>>2) + half*8;
                    float v0 = C[t][f*4 + half*2], v1 = C[t][f*4 + half*2 + 1];
                    if (RELU) { v0 = fmaxf(v0, 0.f); v1 = fmaxf(v1, 0.f); }
                    if (EPIRES) {
                        float2 r2 = *(const float2*)(resid + (size_t)row*LD + col);
                        if (RESBN) {
                            r2.x = r2.x*scR[t*8+(l&3)*2]   + shR[t*8+(l&3)*2];
                            r2.y = r2.y*scR[t*8+(l&3)*2+1] + shR[t*8+(l&3)*2+1];
                        }
                        v0 += r2.x; v1 += r2.y;
                        sA[t][0] += v0; qA[t][0] += v0*v0;
                        sA[t][1] += v1; qA[t][1] += v1*v1;
                    }
                    *(float2*)(out + (size_t)row*LD + col) = make_float2(v0, v1);
                }
        }
    }
    if (EPIRES) {
#pragma unroll
        for (int t = 0; t < NT; t++)
#pragma unroll
            for (int j = 0; j < 2; j++) {
                float s = sA[t][j], q = qA[t][j];
                s += __shfl_xor_sync(0xffffffffu, s, 4);
                q += __shfl_xor_sync(0xffffffffu, q, 4);
                s += __shfl_xor_sync(0xffffffffu, s, 8);
                q += __shfl_xor_sync(0xffffffffu, q, 8);
                s += __shfl_xor_sync(0xffffffffu, s, 16);
                q += __shfl_xor_sync(0xffffffffu, q, 16);
                if (l < 4) {
                    atomicAdd(&sS[t*8 + l*2 + j], s);
                    atomicAdd(&sQ[t*8 + l*2 + j], q);
                }
            }
        __syncthreads();
        for (int c = tid; c < NT*8; c += THREADS) {
            atomicAdd(&g_S[statSlot][n0 + c],  sS[c]);
            atomicAdd(&g_Qs[statSlot][n0 + c], sQ[c]);
        }
    }
}

template<int DIN,int NT,int RPW,bool RELU,bool INBN,bool EPIRES,bool RESBN,int THREADS>
static void tgemm(dim3 grid, const float* in, const float* W, const float* bias,
                  float* out, int M, int WLD, int LD,
                  const float* gaIn = nullptr, const float* beIn = nullptr, int slotIn = 0,
                  const float* resid = nullptr, const float* gaR = nullptr,
                  const float* beR = nullptr, int slotR = 0, int statSlot = 0)
{
    auto kfn = k_tgemm<DIN,NT,RPW,RELU,INBN,EPIRES,RESBN,THREADS>;
    size_t sh = (size_t)(NT*(DIN/16)*128 + 2*DIN + 5*NT*8) * sizeof(float);
    cudaFuncSetAttribute(kfn, cudaFuncAttributeMaxDynamicSharedMemorySize, (int)sh);
    kfn<<<grid, THREADS, sh>>>(in, W, bias, out, M, WLD, LD, gaIn, beIn, slotIn,
                               resid, gaR, beR, slotR, statSlot);
}

// per-edge: score, exp+clip, z scatter, and fused e_lin + residual + BN1e stats
__global__ void k_score(const int* __restrict__ ei, const float* __restrict__ ea) {
    const int tid = threadIdx.x, l = tid & 31;
    int gw = (blockIdx.x*blockDim.x + tid) >> 5, tot = (gridDim.x*blockDim.x) >> 5;
    float2 w[NH];
#pragma unroll
    for (int h = 0; h < NH; h++) w[h] = ((const float2*)(g_Wc + h*EDIM))[l];
    float2 bc = ((const float2*)g_bc)[l];
    float s0 = 0.f, s1 = 0.f, q0 = 0.f, q1 = 0.f;
    for (int e = gw; e < NE; e += tot) {
        int s = ei[e], d = ei[NE + e];
        float4 q = ((const float4*)g_Q)[(size_t)d*32 + l];
        float4 k = ((const float4*)g_K)[(size_t)s*32 + l];
        float4 p = ((const float4*)g_big)[(size_t)e*32 + l];
        float sc = q.x*k.x*p.x + q.y*k.y*p.y + q.z*k.z*p.z + q.w*k.w*p.w;
        sc += __shfl_xor_sync(0xffffffffu, sc, 1);
        sc += __shfl_xor_sync(0xffffffffu, sc, 2);
        sc *= 0.25f;                                   // 1/sqrt(16)
        if ((l & 3) == 0) {
            float ex = __expf(fminf(fmaxf(sc, -5.f), 5.f));
            g_sc[(size_t)e*NH + (l >> 2)] = ex;
            atomicAdd(&g_z[(size_t)d*NH + (l >> 2)], ex);
        }
        float2 acc = bc;
#pragma unroll
        for (int h = 0; h < NH; h++) {
            float sv = __shfl_sync(0xffffffffu, sc, h*4);
            acc.x += sv*w[h].x; acc.y += sv*w[h].y;
        }
        float2 eav = ((const float2*)ea)[(size_t)e*32 + l];
        acc.x += eav.x; acc.y += eav.y;
        ((float2*)g_eres)[(size_t)e*32 + l] = acc;
        s0 += acc.x; q0 += acc.x*acc.x; s1 += acc.y; q1 += acc.y*acc.y;
    }
    atomicAdd(&g_S[0][2*l], s0);   atomicAdd(&g_S[0][2*l+1], s1);
    atomicAdd(&g_Qs[0][2*l], q0);  atomicAdd(&g_Qs[0][2*l+1], q1);
}

// per-edge: alpha = sc/(z+eps); hattn[dst] += V[src]*alpha  (vector RED)
__global__ void k_alpha(const int* __restrict__ ei) {
    const int tid = threadIdx.x, l = tid & 31;
    int gw = (blockIdx.x*blockDim.x + tid) >> 5, tot = (gridDim.x*blockDim.x) >> 5;
    for (int e = gw; e < NE; e += tot) {
        int s = ei[e], d = ei[NE + e];
        int h = l >> 2;
        float a = g_sc[(size_t)e*NH + h] / (g_z[(size_t)d*NH + h] + 1e-6f);
        float4 v = ((const float4*)g_V)[(size_t)s*32 + l];
        atomicAdd(((float4*)(g_hattn + (size_t)d*DDIM)) + l,
                  make_float4(v.x*a, v.y*a, v.z*a, v.w*a));
    }
}

__global__ void k_bnfin(int slot, int C, float invn) {
    int i = threadIdx.x;
    if (i < C) {
        float mu = g_S[slot][i] * invn;
        float var = g_Qs[slot][i] * invn - mu*mu;
        g_mean[slot][i] = mu;
        g_rstd[slot][i] = rsqrtf(var + 1e-5f);
    }
}

template<int C>
__global__ void k_bnapply(const float* __restrict__ in, float* __restrict__ out,
                          const float* __restrict__ ga, const float* __restrict__ be,
                          int slot, size_t total) {
    size_t i0 = (size_t)blockIdx.x*blockDim.x + threadIdx.x;
    size_t st = (size_t)gridDim.x*blockDim.x;
    int c = (int)(i0 & (C - 1));
    float sc = ga[c] * g_rstd[slot][c];
    float sh = be[c] - g_mean[slot][c] * sc;
    for (size_t i = i0; i < total; i += st) out[i] = in[i]*sc + sh;
}

extern "C" void kernel_launch(void* const* d_in, const int* in_sizes, int n_in,
                              void* d_out, int out_size) {
    const float* x   = (const float*)d_in[0];
    const int*   ei  = (const int*)  d_in[1];
    const float* ea  = (const float*)d_in[2];
    const float *Wq = (const float*)d_in[3], *Wk = (const float*)d_in[4];
    const float *Wv = (const float*)d_in[5], *We = (const float*)d_in[6];
    const float *WOh = (const float*)d_in[7],  *bOh = (const float*)d_in[8];
    const float *Wep = (const float*)d_in[9],  *bep = (const float*)d_in[10];
    const float *WOe = (const float*)d_in[11], *bOe = (const float*)d_in[12];
    const float *Wh1 = (const float*)d_in[13], *bh1 = (const float*)d_in[14];
    const float *Wh2 = (const float*)d_in[15], *bh2 = (const float*)d_in[16];
    const float *We1 = (const float*)d_in[17], *be1 = (const float*)d_in[18];
    const float *We2 = (const float*)d_in[19], *be2 = (const float*)d_in[20];
    const float *g1h = (const float*)d_in[21], *B1h = (const float*)d_in[22];
    const float *g1e = (const float*)d_in[23], *B1e = (const float*)d_in[24];
    const float *g2h = (const float*)d_in[25], *B2h = (const float*)d_in[26];
    const float *g2e = (const float*)d_in[27], *B2e = (const float*)d_in[28];
    float* out_h = (float*)d_out;
    float* out_e = out_h + (size_t)NN*DDIM;

    float *pQ, *pK, *pV, *pBig, *pHat, *pHb, *pHmid, *pEres, *pEbn;
    cudaGetSymbolAddress((void**)&pQ, g_Q);
    cudaGetSymbolAddress((void**)&pK, g_K);
    cudaGetSymbolAddress((void**)&pV, g_V);
    cudaGetSymbolAddress((void**)&pBig, g_big);
    cudaGetSymbolAddress((void**)&pHat, g_hattn);
    cudaGetSymbolAddress((void**)&pHb, g_hb);
    cudaGetSymbolAddress((void**)&pHmid, g_hmid);
    cudaGetSymbolAddress((void**)&pEres, g_eres);
    cudaGetSymbolAddress((void**)&pEbn, g_ebn);

    k_init<<<592, 256>>>();
    k_fold<<<1, 512>>>(Wep, bep, WOe, bOe);

    // attention projections (tensor core, split-bf16)
    tgemm<128,8,16,false,false,false,false,256>(dim3(235,2), x, Wq, nullptr, pQ, NN, 128, 128);
    tgemm<128,8,16,false,false,false,false,256>(dim3(235,2), x, Wk, nullptr, pK, NN, 128, 128);
    tgemm<128,8,16,false,false,false,false,256>(dim3(235,2), x, Wv, nullptr, pV, NN, 128, 128);
    tgemm< 64,8,32,false,false,false,false,256>(dim3(296,2), ea, We, nullptr, pBig, NE, 128, 128); // Pe

    // score + softmax denom + fused e_lin/residual/BN1e stats
    k_score<<<592, 256>>>(ei, ea);
    k_bnfin<<<1, 128>>>(0, EDIM, 1.f/NE);
    k_alpha<<<592, 256>>>(ei);

    // h path: Oh proj + residual(x) + BN1h stats fused
    tgemm<128,8,16,false,false,true,false,256>(dim3(235,2), pHat, WOh, bOh, pHb, NN, 128, 128,
        nullptr, nullptr, 0, x, nullptr, nullptr, 0, 2);
    k_bnfin<<<1, 128>>>(2, DDIM, 1.f/NN);
    // FFN1: BN1h applied inline on input rows
    tgemm<128,8,16,true,true,false,false,256>(dim3(235,4), pHb, Wh1, bh1, pHmid, NN, 256, 256,
        g1h, B1h, 2);
    // FFN2: residual = BN1h(hb) recomputed inline; BN2h stats fused
    tgemm<256,8,16,false,false,true,true,256>(dim3(235,2), pHmid, Wh2, bh2, pQ, NN, 128, 128,
        nullptr, nullptr, 0, pHb, g1h, B1h, 2, 3);
    k_bnfin<<<1, 128>>>(3, DDIM, 1.f/NN);
    k_bnapply<128><<<592, 256>>>(pQ, out_h, g2h, B2h, 3, (size_t)NN*DDIM);

    // e path: FFN1 with BN1e inline on eres
    tgemm< 64,8,32,true,true,false,false,256>(dim3(296,2), pEres, We1, be1, pBig, NE, 128, 128,
        g1e, B1e, 0);
    // FFN2: residual = BN1e(eres) inline; BN2e stats fused
    tgemm<128,8,32,false,false,true,true,256>(dim3(296,1), pBig, We2, be2, pEbn, NE, 64, 64,
        nullptr, nullptr, 0, pEres, g1e, B1e, 0, 1);
    k_bnfin<<<1, 128>>>(1, EDIM, 1.f/NE);
    k_bnapply<64><<<592, 256>>>(pEbn, out_e, g2e, B2e, 1, (size_t)NE*EDIM);
}